// round 4
// baseline (speedup 1.0000x reference)
#include <cuda_runtime.h>
#include <cuda_fp16.h>

// ---------------------------------------------------------------------------
// HSLSTMRegressor: 3-layer LSTM (B=128, T=256, IN=64, H=512) + linear head + MSE.
// Persistent fp16-tensor-core kernel, weights resident in SMEM.
// Per-cell GEMM computes the W_hh (recurrent) half FIRST so the global barrier
// for the W_ih (input) half is hidden behind ~6 chunks of MMA. Prefetch depth 2.
// ---------------------------------------------------------------------------

#define Bn   128
#define Tn   256
#define INn  64
#define Hn   512
#define NCTA 128
#define NTHR 256

// SMEM layout (bytes)
#define OFF_W0 0        // 32 x 584 halves  = 37376
#define OFF_W1 37376    // 32 x 1032 halves = 66048
#define OFF_W2 103424   // 32 x 1032 halves = 66048
#define OFF_A  169472   // 2 x 64 x 72 halves = 18432 (double buffer)
#define OFF_G  187904   // 64 x 32 floats   = 8192
#define OFF_C  196096   // 3 x 64 x 8 floats= 6144
#define OFF_B  202240   // 3 x 32 floats    = 384
#define SMEM_TOTAL 202624
#define ABUF_HALVES (64 * 72)

// ---------------- device scratch (static allocations only) -----------------
__device__ __align__(16) __half g_X[Tn * Bn * INn];      // x as [t][b][k], fp16
__device__ __align__(16) __half g_W0[2048 * 576];        // layer0 [Wih|Whh], gate-interleaved
__device__ __align__(16) __half g_W12[2 * 2048 * 1024];  // layers1,2 [Wih|Whh]
__device__ __align__(16) float  g_Bias[3 * 2048];        // b_ih + b_hh, gate-interleaved
__device__ __align__(16) __half g_Hbuf[3 * 2 * Bn * Hn]; // h per layer, ping-pong on t
__device__ unsigned int g_ctr[1024];                     // barrier counters, one per cell

// ---------------------------------------------------------------------------
__global__ void k_init() {
    int idx = blockIdx.x * blockDim.x + threadIdx.x;
    int n = 3 * 2 * Bn * Hn;
    for (int i = idx; i < n; i += gridDim.x * blockDim.x) g_Hbuf[i] = __float2half(0.f);
    if (idx < 1024) g_ctr[idx] = 0u;
}

__global__ void k_conv_x(const float* __restrict__ x) {
    int tot = Tn * Bn * INn;
    for (int i = blockIdx.x * blockDim.x + threadIdx.x; i < tot; i += gridDim.x * blockDim.x) {
        int t = i / (Bn * INn);
        int r = i - t * (Bn * INn);
        int b = r / INn;
        int k = r - b * INn;
        g_X[i] = __float2half(x[(size_t)b * Tn * INn + (size_t)t * INn + k]);
    }
}

// permuted row pr = 4*j + g  <->  source gate row g*512 + j (PyTorch i,f,g,o order)
__global__ void k_conv_w0(const float* __restrict__ wih, const float* __restrict__ whh) {
    int tot = 2048 * 576;
    for (int i = blockIdx.x * blockDim.x + threadIdx.x; i < tot; i += gridDim.x * blockDim.x) {
        int r = i / 576, k = i - r * 576;
        int j = r >> 2, g = r & 3;
        int src = g * 512 + j;
        float v = (k < 64) ? wih[src * 64 + k] : whh[(size_t)src * 512 + (k - 64)];
        g_W0[i] = __float2half(v);
    }
}

__global__ void k_conv_w12(const float* __restrict__ wih, const float* __restrict__ whh) {
    int tot = 2 * 2048 * 1024;
    for (int i = blockIdx.x * blockDim.x + threadIdx.x; i < tot; i += gridDim.x * blockDim.x) {
        int l = i >> 21;
        int rem = i & ((1 << 21) - 1);
        int r = rem >> 10, k = rem & 1023;
        int j = r >> 2, g = r & 3;
        int src = g * 512 + j;
        float v = (k < 512) ? wih[((size_t)l * 2048 + src) * 512 + k]
                            : whh[((size_t)l * 2048 + src) * 512 + (k - 512)];
        g_W12[i] = __float2half(v);
    }
}

__global__ void k_conv_b(const float* __restrict__ bih0, const float* __restrict__ bhh0,
                         const float* __restrict__ bihr, const float* __restrict__ bhhr) {
    int tot = 3 * 2048;
    for (int i = blockIdx.x * blockDim.x + threadIdx.x; i < tot; i += gridDim.x * blockDim.x) {
        int l = i / 2048, r = i - l * 2048;
        int j = r >> 2, g = r & 3;
        int src = g * 512 + j;
        float v = (l == 0) ? (bih0[src] + bhh0[src])
                           : (bihr[(l - 1) * 2048 + src] + bhhr[(l - 1) * 2048 + src]);
        g_Bias[i] = v;
    }
}

// ---------------------------------------------------------------------------
__device__ __forceinline__ void mma16816(float* c,
                                         unsigned a0, unsigned a1, unsigned a2, unsigned a3,
                                         unsigned b0, unsigned b1) {
    asm volatile(
        "mma.sync.aligned.m16n8k16.row.col.f32.f16.f16.f32 "
        "{%0,%1,%2,%3}, {%4,%5,%6,%7}, {%8,%9}, {%0,%1,%2,%3};\n"
        : "+f"(c[0]), "+f"(c[1]), "+f"(c[2]), "+f"(c[3])
        : "r"(a0), "r"(a1), "r"(a2), "r"(a3), "r"(b0), "r"(b1));
}

__device__ __forceinline__ float sigmoidf_(float x) { return 1.f / (1.f + __expf(-x)); }
__device__ __forceinline__ float tanh_fast(float x) {
    float r;
    asm("tanh.approx.f32 %0, %1;" : "=f"(r) : "f"(x));
    return r;
}

__global__ void __launch_bounds__(NTHR, 1) k_lstm() {
    extern __shared__ __align__(16) unsigned char smraw[];
    __half* sW0 = (__half*)(smraw + OFF_W0);
    __half* sW1 = (__half*)(smraw + OFF_W1);
    __half* sW2 = (__half*)(smraw + OFF_W2);
    __half* sA  = (__half*)(smraw + OFF_A);
    float*  sG  = (float*)(smraw + OFF_G);
    float*  sC  = (float*)(smraw + OFF_C);
    float*  sB  = (float*)(smraw + OFF_B);

    const int tid   = threadIdx.x;
    const int cta   = blockIdx.x;
    const int mbase = (cta & 1) * 64;   // batch-row half
    const int cg    = cta >> 1;         // column group: h-cols [cg*8, cg*8+8)
    const int lane  = tid & 31;
    const int wid   = tid >> 5;
    const int mrow0 = (wid & 3) * 16;   // warp's 16 batch rows within the 64-slice
    const int ng0   = (wid >> 2) * 16;  // warp's 16 gate rows within the 32-slice
    const int lg    = lane >> 2;
    const int lt2   = (lane & 3) * 2;

    // ---- load this CTA's weight slice (all 3 layers) into SMEM, once ----
    for (int i = tid; i < 32 * 72; i += NTHR) {              // layer0: 576 halves/row
        int r = i / 72, s = i - r * 72;
        *(uint4*)(sW0 + r * 584 + s * 8) =
            *(const uint4*)(g_W0 + ((size_t)(cg * 32 + r)) * 576 + s * 8);
    }
    for (int i = tid; i < 32 * 128; i += NTHR) {             // layers1,2: 1024 halves/row
        int r = i >> 7, s = i & 127;
        *(uint4*)(sW1 + r * 1032 + s * 8) =
            *(const uint4*)(g_W12 + ((size_t)(cg * 32 + r)) * 1024 + s * 8);
        *(uint4*)(sW2 + r * 1032 + s * 8) =
            *(const uint4*)(g_W12 + ((size_t)(2048 + cg * 32 + r)) * 1024 + s * 8);
    }
    for (int i = tid; i < 96; i += NTHR) {
        int l = i >> 5, r = i & 31;
        sB[i] = g_Bias[l * 2048 + cg * 32 + r];
    }
    for (int i = tid; i < 3 * 64 * 8; i += NTHR) sC[i] = 0.f;
    __syncthreads();

    const int arow = tid >> 2;          // A staging: 64 rows x 64 cols per chunk
    const int acs  = (tid & 3) << 4;
    const int NB   = 8;                 // recurrent (W_hh) chunks come first

    for (int t = 0; t < Tn; ++t) {
        for (int l = 0; l < 3; ++l) {
            const int s = t * 3 + l;
            const __half* srcA;
            int strideA, KA;
            if (l == 0) { srcA = g_X + (size_t)t * Bn * INn; strideA = INn; KA = INn; }
            else        { srcA = g_Hbuf + ((size_t)((l - 1) * 2 + (t & 1))) * Bn * Hn;
                          strideA = Hn; KA = Hn; }
            const __half* srcB = g_Hbuf + ((size_t)(l * 2 + ((t & 1) ^ 1))) * Bn * Hn;
            const __half* wbase = (l == 0) ? sW0 : ((l == 1) ? sW1 : sW2);
            const int wstr = (l == 0) ? 584 : 1032;
            const int nch = NB + (KA >> 6);     // 9 (layer0) or 16 chunks of K=64

            float acc0[4] = {0.f, 0.f, 0.f, 0.f};
            float acc1[4] = {0.f, 0.f, 0.f, 0.f};

            // chunk c: c<NB -> recurrent h^l(t-1) cols c*64; c>=NB -> input cols (c-NB)*64
            uint4 v0[2], v1[2];
            {   // prologue: prefetch chunks 0,1 (both recurrent, always ready)
                const __half* p0 = srcB + (size_t)(mbase + arow) * Hn + acs;
                v0[0] = __ldcg((const uint4*)p0);
                v1[0] = __ldcg((const uint4*)(p0 + 8));
                const __half* p1 = srcB + (size_t)(mbase + arow) * Hn + 64 + acs;
                v0[1] = __ldcg((const uint4*)p1);
                v1[1] = __ldcg((const uint4*)(p1 + 8));
            }

            for (int ch = 0; ch < nch; ++ch) {
                __half* abuf = sA + (ch & 1) * ABUF_HALVES;
                *(uint4*)(abuf + arow * 72 + acs)     = v0[ch & 1];
                *(uint4*)(abuf + arow * 72 + acs + 8) = v1[ch & 1];
                __syncthreads();

                // barrier wait for h^{l-1}(t), just before first A-chunk prefetch
                if (l > 0 && ch + 2 == NB) {
                    if (tid == 0) {
                        volatile unsigned* pc = &g_ctr[s - 1];
                        long long spins = 0;
                        while (*pc < (unsigned)NCTA) {
                            __nanosleep(32);
                            if (++spins > (1LL << 28)) __trap();
                        }
                        __threadfence();
                    }
                    __syncthreads();
                }

                // prefetch chunk ch+2 while MMAs run on chunk ch
                if (ch + 2 < nch) {
                    int c = ch + 2;
                    const __half* p;
                    if (c < NB) p = srcB + (size_t)(mbase + arow) * Hn + (c << 6) + acs;
                    else        p = srcA + (size_t)(mbase + arow) * strideA + ((c - NB) << 6) + acs;
                    v0[ch & 1] = __ldcg((const uint4*)p);
                    v1[ch & 1] = __ldcg((const uint4*)(p + 8));
                }

                const int kbw = (ch < NB) ? (KA + (ch << 6)) : ((ch - NB) << 6);
#pragma unroll
                for (int kk = 0; kk < 64; kk += 16) {
                    unsigned a0 = *(const unsigned*)(abuf + (mrow0 + lg)     * 72 + kk + lt2);
                    unsigned a1 = *(const unsigned*)(abuf + (mrow0 + lg + 8) * 72 + kk + lt2);
                    unsigned a2 = *(const unsigned*)(abuf + (mrow0 + lg)     * 72 + kk + lt2 + 8);
                    unsigned a3 = *(const unsigned*)(abuf + (mrow0 + lg + 8) * 72 + kk + lt2 + 8);
                    {
                        const __half* wp = wbase + (ng0 + lg) * wstr + kbw + kk + lt2;
                        unsigned b0 = *(const unsigned*)wp;
                        unsigned b1 = *(const unsigned*)(wp + 8);
                        mma16816(acc0, a0, a1, a2, a3, b0, b1);
                    }
                    {
                        const __half* wp = wbase + (ng0 + 8 + lg) * wstr + kbw + kk + lt2;
                        unsigned b0 = *(const unsigned*)wp;
                        unsigned b1 = *(const unsigned*)(wp + 8);
                        mma16816(acc1, a0, a1, a2, a3, b0, b1);
                    }
                }
            }
            __syncthreads();   // last MMA reads done before sG (and next-cell sA) writes

            // ---- dump gate pre-activations to SMEM ----
            {
                int m0 = mrow0 + lg;
                int nc = ng0 + lt2;
                sG[m0 * 32 + nc]           = acc0[0];
                sG[m0 * 32 + nc + 1]       = acc0[1];
                sG[(m0 + 8) * 32 + nc]     = acc0[2];
                sG[(m0 + 8) * 32 + nc + 1] = acc0[3];
                sG[m0 * 32 + nc + 8]       = acc1[0];
                sG[m0 * 32 + nc + 9]       = acc1[1];
                sG[(m0 + 8) * 32 + nc + 8] = acc1[2];
                sG[(m0 + 8) * 32 + nc + 9] = acc1[3];
            }
            __syncthreads();

            // ---- elementwise LSTM cell for the CTA's 64x8 (batch, h-col) tile ----
            __half* hdst = g_Hbuf + ((size_t)(l * 2 + (t & 1))) * Bn * Hn;
            for (int idx = tid; idx < 512; idx += NTHR) {
                int m = idx >> 3, j = idx & 7;
                float gi = sG[m * 32 + 4 * j + 0] + sB[l * 32 + 4 * j + 0];
                float gf = sG[m * 32 + 4 * j + 1] + sB[l * 32 + 4 * j + 1];
                float gg = sG[m * 32 + 4 * j + 2] + sB[l * 32 + 4 * j + 2];
                float go = sG[m * 32 + 4 * j + 3] + sB[l * 32 + 4 * j + 3];
                float cp = sC[(l * 64 + m) * 8 + j];
                float cn = sigmoidf_(gf) * cp + sigmoidf_(gi) * tanh_fast(gg);
                float hn = sigmoidf_(go) * tanh_fast(cn);
                sC[(l * 64 + m) * 8 + j] = cn;
                hdst[(size_t)(mbase + m) * Hn + cg * 8 + j] = __float2half(hn);
            }
            __threadfence();

            // ---- split-phase arrive (wait happens inside NEXT cell's chunk loop) ----
            __syncthreads();                 // all h writes of this CTA done
            if (tid == 0) atomicAdd(&g_ctr[s], 1u);
        }
    }
}

// ---------------------------------------------------------------------------
__global__ void k_out(const float* __restrict__ wout, const float* __restrict__ bout,
                      const float* __restrict__ y, float* __restrict__ out, int out_size) {
    __shared__ float sred[128];
    int b = threadIdx.x;
    const __half* h = g_Hbuf + ((size_t)(2 * 2 + ((Tn - 1) & 1))) * Bn * Hn + (size_t)b * Hn;
    float s = 0.f;
    for (int j = 0; j < Hn; ++j) s += __half2float(h[j]) * wout[j];
    s += bout[0];
    float d = s - y[b];
    sred[b] = d * d;
    __syncthreads();
    for (int st = 64; st > 0; st >>= 1) {
        if (b < st) sred[b] += sred[b + st];
        __syncthreads();
    }
    float loss = sred[0] * (1.f / 128.f);
    if (out_size == 1) {
        if (b == 0) out[0] = loss;
    } else {
        if (b < out_size) out[b] = s;
        if (b == 0 && out_size > Bn) out[Bn] = loss;
    }
}

// ---------------------------------------------------------------------------
extern "C" void kernel_launch(void* const* d_in, const int* in_sizes, int n_in,
                              void* d_out, int out_size) {
    const float* x    = (const float*)d_in[0];
    const float* y    = (const float*)d_in[1];
    const float* wih0 = (const float*)d_in[2];
    const float* whh0 = (const float*)d_in[3];
    const float* bih0 = (const float*)d_in[4];
    const float* bhh0 = (const float*)d_in[5];
    const float* wihr = (const float*)d_in[6];
    const float* whhr = (const float*)d_in[7];
    const float* bihr = (const float*)d_in[8];
    const float* bhhr = (const float*)d_in[9];
    const float* wout = (const float*)d_in[10];
    const float* bout = (const float*)d_in[11];

    cudaFuncSetAttribute(k_lstm, cudaFuncAttributeMaxDynamicSharedMemorySize, SMEM_TOTAL);

    k_init<<<512, 256>>>();
    k_conv_x<<<512, 256>>>(x);
    k_conv_w0<<<512, 256>>>(wih0, whh0);
    k_conv_w12<<<1024, 256>>>(wihr, whhr);
    k_conv_b<<<24, 256>>>(bih0, bhh0, bihr, bhhr);
    k_lstm<<<NCTA, NTHR, SMEM_TOTAL>>>();
    k_out<<<1, 128>>>(wout, bout, y, (float*)d_out, out_size);
}

// round 5
// speedup vs baseline: 1.3142x; 1.3142x over previous
#include <cuda_runtime.h>
#include <cuda_fp16.h>

// ---------------------------------------------------------------------------
// HSLSTMRegressor: 3-layer LSTM (B=128, T=256, IN=64, H=512) + head + MSE.
// Layer-pipelined persistent kernel: 3 groups x 32 CTAs, group g owns layer g.
// Wavefront step k: group g computes timestep t = k - g. One global barrier
// per step -> 258 sequential steps instead of 768. Each CTA: M=128 batch x
// N=64 gate rows x K=(64|512)+512, weights for its layer resident in SMEM.
// ---------------------------------------------------------------------------

#define Bn   128
#define Tn   256
#define INn  64
#define Hn   512
#define NCTA 96          // 3 groups x 32
#define NTHR 256
#define NSTEP (Tn + 2)   // 258 wavefront steps

// SMEM layout (bytes)
#define OFF_W 0          // 64 rows x 1032 halves (max) = 132096
#define OFF_A 132096     // 2 x 128 x 72 halves = 36864
#define OFF_G 168960     // 128 x 64 floats = 32768
#define OFF_C 201728     // 128 x 16 floats = 8192
#define OFF_B 209920     // 64 floats = 256
#define SMEM_TOTAL 210176
#define ABUF_HALVES (128 * 72)

// ---------------- device scratch (static allocations only) -----------------
__device__ __align__(16) __half g_X[Tn * Bn * INn];      // x as [t][b][k], fp16
__device__ __align__(16) __half g_W0[2048 * 576];        // layer0 [Wih|Whh], gate-interleaved
__device__ __align__(16) __half g_W12[2 * 2048 * 1024];  // layers1,2 [Wih|Whh]
__device__ __align__(16) float  g_Bias[3 * 2048];        // b_ih + b_hh, gate-interleaved
__device__ __align__(16) __half g_Hbuf[3 * 2 * Bn * Hn]; // h per layer, ping-pong on t
__device__ unsigned int g_ctr[1024];                     // barrier counters, one per step

// ---------------------------------------------------------------------------
__global__ void k_init() {
    int idx = blockIdx.x * blockDim.x + threadIdx.x;
    int n = 3 * 2 * Bn * Hn;
    for (int i = idx; i < n; i += gridDim.x * blockDim.x) g_Hbuf[i] = __float2half(0.f);
    if (idx < 1024) g_ctr[idx] = 0u;
}

__global__ void k_conv_x(const float* __restrict__ x) {
    int tot = Tn * Bn * INn;
    for (int i = blockIdx.x * blockDim.x + threadIdx.x; i < tot; i += gridDim.x * blockDim.x) {
        int t = i / (Bn * INn);
        int r = i - t * (Bn * INn);
        int b = r / INn;
        int k = r - b * INn;
        g_X[i] = __float2half(x[(size_t)b * Tn * INn + (size_t)t * INn + k]);
    }
}

// permuted row pr = 4*j + g  <->  source gate row g*512 + j (PyTorch i,f,g,o order)
__global__ void k_conv_w0(const float* __restrict__ wih, const float* __restrict__ whh) {
    int tot = 2048 * 576;
    for (int i = blockIdx.x * blockDim.x + threadIdx.x; i < tot; i += gridDim.x * blockDim.x) {
        int r = i / 576, k = i - r * 576;
        int j = r >> 2, g = r & 3;
        int src = g * 512 + j;
        float v = (k < 64) ? wih[src * 64 + k] : whh[(size_t)src * 512 + (k - 64)];
        g_W0[i] = __float2half(v);
    }
}

__global__ void k_conv_w12(const float* __restrict__ wih, const float* __restrict__ whh) {
    int tot = 2 * 2048 * 1024;
    for (int i = blockIdx.x * blockDim.x + threadIdx.x; i < tot; i += gridDim.x * blockDim.x) {
        int l = i >> 21;
        int rem = i & ((1 << 21) - 1);
        int r = rem >> 10, k = rem & 1023;
        int j = r >> 2, g = r & 3;
        int src = g * 512 + j;
        float v = (k < 512) ? wih[((size_t)l * 2048 + src) * 512 + k]
                            : whh[((size_t)l * 2048 + src) * 512 + (k - 512)];
        g_W12[i] = __float2half(v);
    }
}

__global__ void k_conv_b(const float* __restrict__ bih0, const float* __restrict__ bhh0,
                         const float* __restrict__ bihr, const float* __restrict__ bhhr) {
    int tot = 3 * 2048;
    for (int i = blockIdx.x * blockDim.x + threadIdx.x; i < tot; i += gridDim.x * blockDim.x) {
        int l = i / 2048, r = i - l * 2048;
        int j = r >> 2, g = r & 3;
        int src = g * 512 + j;
        float v = (l == 0) ? (bih0[src] + bhh0[src])
                           : (bihr[(l - 1) * 2048 + src] + bhhr[(l - 1) * 2048 + src]);
        g_Bias[i] = v;
    }
}

// ---------------------------------------------------------------------------
__device__ __forceinline__ void mma16816(float* c,
                                         unsigned a0, unsigned a1, unsigned a2, unsigned a3,
                                         unsigned b0, unsigned b1) {
    asm volatile(
        "mma.sync.aligned.m16n8k16.row.col.f32.f16.f16.f32 "
        "{%0,%1,%2,%3}, {%4,%5,%6,%7}, {%8,%9}, {%0,%1,%2,%3};\n"
        : "+f"(c[0]), "+f"(c[1]), "+f"(c[2]), "+f"(c[3])
        : "r"(a0), "r"(a1), "r"(a2), "r"(a3), "r"(b0), "r"(b1));
}

__device__ __forceinline__ float sigmoidf_(float x) { return 1.f / (1.f + __expf(-x)); }
__device__ __forceinline__ float tanh_fast(float x) {
    float r;
    asm("tanh.approx.f32 %0, %1;" : "=f"(r) : "f"(x));
    return r;
}

__global__ void __launch_bounds__(NTHR, 1) k_lstm() {
    extern __shared__ __align__(16) unsigned char smraw[];
    __half* sW = (__half*)(smraw + OFF_W);
    __half* sA = (__half*)(smraw + OFF_A);
    float*  sG = (float*)(smraw + OFF_G);
    float*  sC = (float*)(smraw + OFF_C);
    float*  sB = (float*)(smraw + OFF_B);

    const int tid  = threadIdx.x;
    const int grp  = blockIdx.x >> 5;       // layer this group owns (0..2)
    const int cg   = blockIdx.x & 31;       // col group: h-cols [cg*16, cg*16+16)
    const int lane = tid & 31;
    const int wid  = tid >> 5;
    const int mrow0 = (wid & 3) * 32;       // warp's 32 batch rows (of 128)
    const int ng0   = (wid >> 2) * 32;      // warp's 32 gate rows (of 64)
    const int lg    = lane >> 2;
    const int lt2   = (lane & 3) * 2;

    const int wcols = (grp == 0) ? 576 : 1024;
    const int wstr  = (grp == 0) ? 584 : 1032;
    const __half* gW = (grp == 0) ? g_W0
                      : g_W12 + (size_t)(grp - 1) * 2048 * 1024;

    // ---- load this CTA's 64 gate rows of its layer's weights into SMEM ----
    {
        int qpr = wcols >> 3;               // uint4 per row
        for (int i = tid; i < 64 * qpr; i += NTHR) {
            int r = i / qpr, q = i - r * qpr;
            *(uint4*)(sW + r * wstr + q * 8) =
                *(const uint4*)(gW + ((size_t)(cg * 64 + r)) * wcols + q * 8);
        }
    }
    for (int i = tid; i < 64; i += NTHR) sB[i] = g_Bias[grp * 2048 + cg * 64 + i];
    for (int i = tid; i < 128 * 16; i += NTHR) sC[i] = 0.f;
    __syncthreads();

    const int arow = tid >> 1;              // A staging: 128 rows x 64 cols per chunk
    const int acs  = (tid & 1) << 5;        // 32-half segment per thread

    for (int step = 0; step < NSTEP; ++step) {
        const int t = step - grp;
        if (t >= 0 && t < Tn) {
            const __half* srcA;
            int strideA, nA;
            if (grp == 0) { srcA = g_X + (size_t)t * Bn * INn; strideA = INn; nA = 1; }
            else          { srcA = g_Hbuf + ((size_t)((grp - 1) * 2 + (t & 1))) * Bn * Hn;
                            strideA = Hn; nA = 8; }
            const __half* srcB = g_Hbuf + ((size_t)(grp * 2 + ((t & 1) ^ 1))) * Bn * Hn;
            const int nch = nA + 8;

            float acc[2][4][4];
#pragma unroll
            for (int mi = 0; mi < 2; ++mi)
#pragma unroll
                for (int ni = 0; ni < 4; ++ni)
#pragma unroll
                    for (int q = 0; q < 4; ++q) acc[mi][ni][q] = 0.f;

            // depth-2 register prefetch: v[buf][4 x uint4]
            uint4 v[2][4];
#pragma unroll
            for (int pc = 0; pc < 2; ++pc) {
                const __half* p = (pc < nA)
                    ? srcA + (size_t)arow * strideA + (pc << 6) + acs
                    : srcB + (size_t)arow * Hn + ((pc - nA) << 6) + acs;
#pragma unroll
                for (int q = 0; q < 4; ++q) v[pc][q] = __ldcg((const uint4*)(p + q * 8));
            }

            for (int ch = 0; ch < nch; ++ch) {
                __half* abuf = sA + (ch & 1) * ABUF_HALVES;
                {
                    __half* d = abuf + arow * 72 + acs;
#pragma unroll
                    for (int q = 0; q < 4; ++q) *(uint4*)(d + q * 8) = v[ch & 1][q];
                }
                __syncthreads();

                if (ch + 2 < nch) {
                    int c = ch + 2;
                    const __half* p = (c < nA)
                        ? srcA + (size_t)arow * strideA + (c << 6) + acs
                        : srcB + (size_t)arow * Hn + ((c - nA) << 6) + acs;
#pragma unroll
                    for (int q = 0; q < 4; ++q) v[ch & 1][q] = __ldcg((const uint4*)(p + q * 8));
                }

                const int kbw = ch << 6;    // weight cols are [input | recurrent]
#pragma unroll
                for (int kk = 0; kk < 64; kk += 16) {
                    unsigned a[2][4];
#pragma unroll
                    for (int mi = 0; mi < 2; ++mi) {
                        const __half* ap = abuf + (mrow0 + mi * 16 + lg) * 72 + kk + lt2;
                        a[mi][0] = *(const unsigned*)ap;
                        a[mi][1] = *(const unsigned*)(ap + 8 * 72);
                        a[mi][2] = *(const unsigned*)(ap + 8);
                        a[mi][3] = *(const unsigned*)(ap + 8 * 72 + 8);
                    }
#pragma unroll
                    for (int ni = 0; ni < 4; ++ni) {
                        const __half* wp = sW + (ng0 + ni * 8 + lg) * wstr + kbw + kk + lt2;
                        unsigned b0 = *(const unsigned*)wp;
                        unsigned b1 = *(const unsigned*)(wp + 8);
                        mma16816(acc[0][ni], a[0][0], a[0][1], a[0][2], a[0][3], b0, b1);
                        mma16816(acc[1][ni], a[1][0], a[1][1], a[1][2], a[1][3], b0, b1);
                    }
                }
            }
            __syncthreads();

            // ---- dump gate pre-activations to SMEM ----
#pragma unroll
            for (int mi = 0; mi < 2; ++mi)
#pragma unroll
                for (int ni = 0; ni < 4; ++ni) {
                    int m0 = mrow0 + mi * 16 + lg;
                    int nc = ng0 + ni * 8 + lt2;
                    sG[m0 * 64 + nc]           = acc[mi][ni][0];
                    sG[m0 * 64 + nc + 1]       = acc[mi][ni][1];
                    sG[(m0 + 8) * 64 + nc]     = acc[mi][ni][2];
                    sG[(m0 + 8) * 64 + nc + 1] = acc[mi][ni][3];
                }
            __syncthreads();

            // ---- elementwise LSTM cell: 128 batch x 16 h-cols ----
            __half* hdst = g_Hbuf + ((size_t)(grp * 2 + (t & 1))) * Bn * Hn;
            for (int idx = tid; idx < 128 * 16; idx += NTHR) {
                int m = idx >> 4, jj = idx & 15;
                float gi = sG[m * 64 + 4 * jj + 0] + sB[4 * jj + 0];
                float gf = sG[m * 64 + 4 * jj + 1] + sB[4 * jj + 1];
                float gg = sG[m * 64 + 4 * jj + 2] + sB[4 * jj + 2];
                float go = sG[m * 64 + 4 * jj + 3] + sB[4 * jj + 3];
                float cp = sC[m * 16 + jj];
                float cn = sigmoidf_(gf) * cp + sigmoidf_(gi) * tanh_fast(gg);
                float hn = sigmoidf_(go) * tanh_fast(cn);
                sC[m * 16 + jj] = cn;
                hdst[(size_t)m * Hn + cg * 16 + jj] = __float2half(hn);
            }
        }

        // ---- global wavefront barrier (all 96 CTAs, every step) ----
        __syncthreads();
        if (tid == 0) {
            __threadfence();
            atomicAdd(&g_ctr[step], 1u);
            volatile unsigned* pc = &g_ctr[step];
            long long spins = 0;
            while (*pc < (unsigned)NCTA) {
                __nanosleep(32);
                if (++spins > (1LL << 28)) __trap();   // fail loud, never hang
            }
            __threadfence();
        }
        __syncthreads();
    }
}

// ---------------------------------------------------------------------------
__global__ void k_out(const float* __restrict__ wout, const float* __restrict__ bout,
                      const float* __restrict__ y, float* __restrict__ out, int out_size) {
    __shared__ float sred[128];
    int b = threadIdx.x;
    const __half* h = g_Hbuf + ((size_t)(2 * 2 + ((Tn - 1) & 1))) * Bn * Hn + (size_t)b * Hn;
    float s = 0.f;
    for (int j = 0; j < Hn; ++j) s += __half2float(h[j]) * wout[j];
    s += bout[0];
    float d = s - y[b];
    sred[b] = d * d;
    __syncthreads();
    for (int st = 64; st > 0; st >>= 1) {
        if (b < st) sred[b] += sred[b + st];
        __syncthreads();
    }
    float loss = sred[0] * (1.f / 128.f);
    if (out_size == 1) {
        if (b == 0) out[0] = loss;
    } else {
        if (b < out_size) out[b] = s;
        if (b == 0 && out_size > Bn) out[Bn] = loss;
    }
}

// ---------------------------------------------------------------------------
extern "C" void kernel_launch(void* const* d_in, const int* in_sizes, int n_in,
                              void* d_out, int out_size) {
    const float* x    = (const float*)d_in[0];
    const float* y    = (const float*)d_in[1];
    const float* wih0 = (const float*)d_in[2];
    const float* whh0 = (const float*)d_in[3];
    const float* bih0 = (const float*)d_in[4];
    const float* bhh0 = (const float*)d_in[5];
    const float* wihr = (const float*)d_in[6];
    const float* whhr = (const float*)d_in[7];
    const float* bihr = (const float*)d_in[8];
    const float* bhhr = (const float*)d_in[9];
    const float* wout = (const float*)d_in[10];
    const float* bout = (const float*)d_in[11];

    cudaFuncSetAttribute(k_lstm, cudaFuncAttributeMaxDynamicSharedMemorySize, SMEM_TOTAL);

    k_init<<<512, 256>>>();
    k_conv_x<<<512, 256>>>(x);
    k_conv_w0<<<512, 256>>>(wih0, whh0);
    k_conv_w12<<<1024, 256>>>(wihr, whhr);
    k_conv_b<<<24, 256>>>(bih0, bhh0, bihr, bhhr);
    k_lstm<<<NCTA, NTHR, SMEM_TOTAL>>>();
    k_out<<<1, 128>>>(wout, bout, y, (float*)d_out, out_size);
}

// round 6
// speedup vs baseline: 1.7204x; 1.3091x over previous
#include <cuda_runtime.h>
#include <cuda_fp16.h>

// ---------------------------------------------------------------------------
// HSLSTMRegressor: 3-layer LSTM (B=128, T=256, IN=64, H=512) + head + MSE.
// Layer-pipelined persistent kernel: 3 groups x 32 CTAs, group g owns layer g.
// 258 wavefront steps, one (4-way split) global barrier per step.
// Fragments loaded via ldmatrix.x4 (4x fewer LSU issues than LDS.32).
// Launch order arranged so k_lstm is launch index 3 (the ncu capture slot).
// ---------------------------------------------------------------------------

#define Bn   128
#define Tn   256
#define INn  64
#define Hn   512
#define NCTA 96          // 3 groups x 32
#define NTHR 256
#define NSTEP (Tn + 2)   // 258 wavefront steps

// SMEM layout (bytes)
#define OFF_W 0          // 64 rows x 1032 halves (max) = 132096
#define OFF_A 132096     // 2 x 128 x 72 halves = 36864
#define OFF_G 168960     // 128 x 64 floats = 32768
#define OFF_C 201728     // 128 x 16 floats = 8192
#define OFF_B 209920     // 64 floats = 256
#define SMEM_TOTAL 210176
#define ABUF_BYTES (128 * 72 * 2)

// ---------------- device scratch (static allocations only) -----------------
__device__ __align__(16) __half g_X[Tn * Bn * INn];      // x as [t][b][k], fp16
__device__ __align__(16) __half g_W0[2048 * 576];        // layer0 [Wih|Whh], gate-interleaved
__device__ __align__(16) __half g_W12[2 * 2048 * 1024];  // layers1,2 [Wih|Whh]
__device__ __align__(16) float  g_Bias[3 * 2048];        // b_ih + b_hh, gate-interleaved
__device__ __align__(16) __half g_Hbuf[3 * 2 * Bn * Hn]; // h per layer, ping-pong on t
__device__ unsigned int g_ctr[NSTEP * 128];              // 4 counters/step, 128B apart

// ---------------------------------------------------------------------------
// launch 0: zero h/c state + barrier counters, build combined bias
__global__ void k_init_misc(const float* __restrict__ bih0, const float* __restrict__ bhh0,
                            const float* __restrict__ bihr, const float* __restrict__ bhhr) {
    int idx = blockIdx.x * blockDim.x + threadIdx.x;
    int stride = gridDim.x * blockDim.x;
    for (int i = idx; i < 3 * 2 * Bn * Hn; i += stride) g_Hbuf[i] = __float2half(0.f);
    for (int i = idx; i < NSTEP * 128; i += stride) g_ctr[i] = 0u;
    for (int i = idx; i < 3 * 2048; i += stride) {
        int l = i / 2048, r = i - l * 2048;
        int j = r >> 2, g = r & 3;
        int src = g * 512 + j;
        float v = (l == 0) ? (bih0[src] + bhh0[src])
                           : (bihr[(l - 1) * 2048 + src] + bhhr[(l - 1) * 2048 + src]);
        g_Bias[i] = v;
    }
}

// launch 1: x -> [t][b][k] fp16
__global__ void k_conv_x(const float* __restrict__ x) {
    int tot = Tn * Bn * INn;
    for (int i = blockIdx.x * blockDim.x + threadIdx.x; i < tot; i += gridDim.x * blockDim.x) {
        int t = i / (Bn * INn);
        int r = i - t * (Bn * INn);
        int b = r / INn;
        int k = r - b * INn;
        g_X[i] = __float2half(x[(size_t)b * Tn * INn + (size_t)t * INn + k]);
    }
}

// launch 2: all weights -> fp16, gate-interleaved rows (pr = 4*j + g)
__global__ void k_conv_w(const float* __restrict__ wih0, const float* __restrict__ whh0,
                         const float* __restrict__ wihr, const float* __restrict__ whhr) {
    const int W0TOT = 2048 * 576;
    const int tot = W0TOT + 2 * 2048 * 1024;
    for (int i = blockIdx.x * blockDim.x + threadIdx.x; i < tot; i += gridDim.x * blockDim.x) {
        if (i < W0TOT) {
            int r = i / 576, k = i - r * 576;
            int j = r >> 2, g = r & 3;
            int src = g * 512 + j;
            float v = (k < 64) ? wih0[src * 64 + k] : whh0[(size_t)src * 512 + (k - 64)];
            g_W0[i] = __float2half(v);
        } else {
            int rem = i - W0TOT;
            int l = rem >> 21;
            int rr = rem & ((1 << 21) - 1);
            int r = rr >> 10, k = rr & 1023;
            int j = r >> 2, g = r & 3;
            int src = g * 512 + j;
            float v = (k < 512) ? wihr[((size_t)l * 2048 + src) * 512 + k]
                                : whhr[((size_t)l * 2048 + src) * 512 + (k - 512)];
            g_W12[rem] = __float2half(v);
        }
    }
}

// ---------------------------------------------------------------------------
__device__ __forceinline__ void mma16816(float* c,
                                         unsigned a0, unsigned a1, unsigned a2, unsigned a3,
                                         unsigned b0, unsigned b1) {
    asm volatile(
        "mma.sync.aligned.m16n8k16.row.col.f32.f16.f16.f32 "
        "{%0,%1,%2,%3}, {%4,%5,%6,%7}, {%8,%9}, {%0,%1,%2,%3};\n"
        : "+f"(c[0]), "+f"(c[1]), "+f"(c[2]), "+f"(c[3])
        : "r"(a0), "r"(a1), "r"(a2), "r"(a3), "r"(b0), "r"(b1));
}

__device__ __forceinline__ void ldsm_x4(unsigned addr, unsigned& r0, unsigned& r1,
                                        unsigned& r2, unsigned& r3) {
    asm volatile("ldmatrix.sync.aligned.m8n8.x4.shared.b16 {%0,%1,%2,%3}, [%4];"
                 : "=r"(r0), "=r"(r1), "=r"(r2), "=r"(r3) : "r"(addr));
}

__device__ __forceinline__ float sigmoidf_(float x) { return 1.f / (1.f + __expf(-x)); }
__device__ __forceinline__ float tanh_fast(float x) {
    float r;
    asm("tanh.approx.f32 %0, %1;" : "=f"(r) : "f"(x));
    return r;
}

// launch 3 (== the ncu capture slot): the persistent LSTM kernel
__global__ void __launch_bounds__(NTHR, 1) k_lstm() {
    extern __shared__ __align__(16) unsigned char smraw[];
    __half* sW = (__half*)(smraw + OFF_W);
    __half* sA = (__half*)(smraw + OFF_A);
    float*  sG = (float*)(smraw + OFF_G);
    float*  sC = (float*)(smraw + OFF_C);
    float*  sB = (float*)(smraw + OFF_B);

    const int tid  = threadIdx.x;
    const int grp  = blockIdx.x >> 5;       // layer this group owns (0..2)
    const int cg   = blockIdx.x & 31;       // col group: h-cols [cg*16, cg*16+16)
    const int lane = tid & 31;
    const int wid  = tid >> 5;
    const int mrow0 = (wid & 3) * 32;       // warp's 32 batch rows (of 128)
    const int ng0   = (wid >> 2) * 32;      // warp's 32 gate rows (of 64)
    const int lg    = lane >> 2;
    const int lt2   = (lane & 3) * 2;

    const int wcols = (grp == 0) ? 576 : 1024;
    const int wstr  = (grp == 0) ? 584 : 1032;
    const __half* gW = (grp == 0) ? g_W0
                      : g_W12 + (size_t)(grp - 1) * 2048 * 1024;

    // ---- load this CTA's 64 gate rows of its layer's weights into SMEM ----
    {
        int qpr = wcols >> 3;               // uint4 per row
        for (int i = tid; i < 64 * qpr; i += NTHR) {
            int r = i / qpr, q = i - r * qpr;
            *(uint4*)(sW + r * wstr + q * 8) =
                *(const uint4*)(gW + ((size_t)(cg * 64 + r)) * wcols + q * 8);
        }
    }
    for (int i = tid; i < 64; i += NTHR) sB[i] = g_Bias[grp * 2048 + cg * 64 + i];
    for (int i = tid; i < 128 * 16; i += NTHR) sC[i] = 0.f;
    __syncthreads();

    const int arow = tid >> 1;              // A staging: 128 rows x 64 cols per chunk
    const int acs  = (tid & 1) << 5;        // 32-half segment per thread

    // ldmatrix per-lane address components
    const unsigned sA_s = (unsigned)__cvta_generic_to_shared(sA);
    const unsigned sW_s = (unsigned)__cvta_generic_to_shared(sW);
    // A: quad q = lane>>3: q0 rows+0 k+0, q1 rows+8 k+0, q2 rows+0 k+8, q3 rows+8 k+8
    const int a_r   = ((lane >> 3) & 1) * 8 + (lane & 7);
    const int a_k   = (lane >> 4) * 8;
    const unsigned a_off = (unsigned)(((mrow0 + a_r) * 72 + a_k) * 2);
    // B: q0 (n+0,k+0), q1 (n+0,k+8), q2 (n+8,k+0), q3 (n+8,k+8)
    const int b_n   = (lane & 7) + ((lane >> 4) & 1) * 8;
    const int b_k   = ((lane >> 3) & 1) * 8;
    const unsigned b_off = (unsigned)(((ng0 + b_n) * wstr + b_k) * 2);

    for (int step = 0; step < NSTEP; ++step) {
        const int t = step - grp;
        if (t >= 0 && t < Tn) {
            const __half* srcA;
            int strideA, nA;
            if (grp == 0) { srcA = g_X + (size_t)t * Bn * INn; strideA = INn; nA = 1; }
            else          { srcA = g_Hbuf + ((size_t)((grp - 1) * 2 + (t & 1))) * Bn * Hn;
                            strideA = Hn; nA = 8; }
            const __half* srcB = g_Hbuf + ((size_t)(grp * 2 + ((t & 1) ^ 1))) * Bn * Hn;
            const int nch = nA + 8;

            float acc[2][4][4];
#pragma unroll
            for (int mi = 0; mi < 2; ++mi)
#pragma unroll
                for (int ni = 0; ni < 4; ++ni)
#pragma unroll
                    for (int q = 0; q < 4; ++q) acc[mi][ni][q] = 0.f;

            // depth-2 register prefetch
            uint4 v[2][4];
#pragma unroll
            for (int pc = 0; pc < 2; ++pc) {
                const __half* p = (pc < nA)
                    ? srcA + (size_t)arow * strideA + (pc << 6) + acs
                    : srcB + (size_t)arow * Hn + ((pc - nA) << 6) + acs;
#pragma unroll
                for (int q = 0; q < 4; ++q) v[pc][q] = __ldcg((const uint4*)(p + q * 8));
            }

            for (int ch = 0; ch < nch; ++ch) {
                {
                    __half* d = sA + (ch & 1) * (ABUF_BYTES / 2) + arow * 72 + acs;
#pragma unroll
                    for (int q = 0; q < 4; ++q) *(uint4*)(d + q * 8) = v[ch & 1][q];
                }
                __syncthreads();

                if (ch + 2 < nch) {
                    int c = ch + 2;
                    const __half* p = (c < nA)
                        ? srcA + (size_t)arow * strideA + (c << 6) + acs
                        : srcB + (size_t)arow * Hn + ((c - nA) << 6) + acs;
#pragma unroll
                    for (int q = 0; q < 4; ++q) v[ch & 1][q] = __ldcg((const uint4*)(p + q * 8));
                }

                const unsigned abase = sA_s + (unsigned)((ch & 1) * ABUF_BYTES) + a_off;
                const unsigned bbase = sW_s + b_off + (unsigned)((ch << 6) * 2);
#pragma unroll
                for (int kk = 0; kk < 64; kk += 16) {
                    unsigned a0[4], a1[4], bb[2][4];
                    ldsm_x4(abase + kk * 2,            a0[0], a0[1], a0[2], a0[3]);
                    ldsm_x4(abase + 16 * 144 + kk * 2, a1[0], a1[1], a1[2], a1[3]);
                    ldsm_x4(bbase + kk * 2,                    bb[0][0], bb[0][1], bb[0][2], bb[0][3]);
                    ldsm_x4(bbase + 16 * wstr * 2 + kk * 2,    bb[1][0], bb[1][1], bb[1][2], bb[1][3]);
#pragma unroll
                    for (int p = 0; p < 2; ++p) {
                        mma16816(acc[0][2 * p],     a0[0], a0[1], a0[2], a0[3], bb[p][0], bb[p][1]);
                        mma16816(acc[1][2 * p],     a1[0], a1[1], a1[2], a1[3], bb[p][0], bb[p][1]);
                        mma16816(acc[0][2 * p + 1], a0[0], a0[1], a0[2], a0[3], bb[p][2], bb[p][3]);
                        mma16816(acc[1][2 * p + 1], a1[0], a1[1], a1[2], a1[3], bb[p][2], bb[p][3]);
                    }
                }
            }
            __syncthreads();

            // ---- dump gate pre-activations to SMEM ----
#pragma unroll
            for (int mi = 0; mi < 2; ++mi)
#pragma unroll
                for (int ni = 0; ni < 4; ++ni) {
                    int m0 = mrow0 + mi * 16 + lg;
                    int nc = ng0 + ni * 8 + lt2;
                    sG[m0 * 64 + nc]           = acc[mi][ni][0];
                    sG[m0 * 64 + nc + 1]       = acc[mi][ni][1];
                    sG[(m0 + 8) * 64 + nc]     = acc[mi][ni][2];
                    sG[(m0 + 8) * 64 + nc + 1] = acc[mi][ni][3];
                }
            __syncthreads();

            // ---- elementwise LSTM cell: 128 batch x 16 h-cols ----
            __half* hdst = g_Hbuf + ((size_t)(grp * 2 + (t & 1))) * Bn * Hn;
            for (int idx = tid; idx < 128 * 16; idx += NTHR) {
                int m = idx >> 4, jj = idx & 15;
                float gi = sG[m * 64 + 4 * jj + 0] + sB[4 * jj + 0];
                float gf = sG[m * 64 + 4 * jj + 1] + sB[4 * jj + 1];
                float gg = sG[m * 64 + 4 * jj + 2] + sB[4 * jj + 2];
                float go = sG[m * 64 + 4 * jj + 3] + sB[4 * jj + 3];
                float cp = sC[m * 16 + jj];
                float cn = sigmoidf_(gf) * cp + sigmoidf_(gi) * tanh_fast(gg);
                float hn = sigmoidf_(go) * tanh_fast(cn);
                sC[m * 16 + jj] = cn;
                hdst[(size_t)m * Hn + cg * 16 + jj] = __float2half(hn);
            }
        }

        // ---- global wavefront barrier: 4-way split counters ----
        __threadfence();                    // release h-writes (all threads)
        __syncthreads();
        if (tid == 0)
            atomicAdd(&g_ctr[step * 128 + (blockIdx.x & 3) * 32], 1u);
        if (tid < 4) {
            volatile unsigned* pc = &g_ctr[step * 128 + tid * 32];
            long long spins = 0;
            while (*pc < (unsigned)(NCTA / 4)) {
                __nanosleep(20);
                if (++spins > (1LL << 28)) __trap();   // fail loud, never hang
            }
            __threadfence();                // acquire before reading peer h
        }
        __syncthreads();
    }
}

// ---------------------------------------------------------------------------
// launch 4: output head + MSE loss
__global__ void k_out(const float* __restrict__ wout, const float* __restrict__ bout,
                      const float* __restrict__ y, float* __restrict__ out, int out_size) {
    __shared__ float sred[128];
    int b = threadIdx.x;
    const __half* h = g_Hbuf + ((size_t)(2 * 2 + ((Tn - 1) & 1))) * Bn * Hn + (size_t)b * Hn;
    float s = 0.f;
    for (int j = 0; j < Hn; ++j) s += __half2float(h[j]) * wout[j];
    s += bout[0];
    float d = s - y[b];
    sred[b] = d * d;
    __syncthreads();
    for (int st = 64; st > 0; st >>= 1) {
        if (b < st) sred[b] += sred[b + st];
        __syncthreads();
    }
    float loss = sred[0] * (1.f / 128.f);
    if (out_size == 1) {
        if (b == 0) out[0] = loss;
    } else {
        if (b < out_size) out[b] = s;
        if (b == 0 && out_size > Bn) out[Bn] = loss;
    }
}

// ---------------------------------------------------------------------------
extern "C" void kernel_launch(void* const* d_in, const int* in_sizes, int n_in,
                              void* d_out, int out_size) {
    const float* x    = (const float*)d_in[0];
    const float* y    = (const float*)d_in[1];
    const float* wih0 = (const float*)d_in[2];
    const float* whh0 = (const float*)d_in[3];
    const float* bih0 = (const float*)d_in[4];
    const float* bhh0 = (const float*)d_in[5];
    const float* wihr = (const float*)d_in[6];
    const float* whhr = (const float*)d_in[7];
    const float* bihr = (const float*)d_in[8];
    const float* bhhr = (const float*)d_in[9];
    const float* wout = (const float*)d_in[10];
    const float* bout = (const float*)d_in[11];

    cudaFuncSetAttribute(k_lstm, cudaFuncAttributeMaxDynamicSharedMemorySize, SMEM_TOTAL);

    k_init_misc<<<512, 256>>>(bih0, bhh0, bihr, bhhr);   // launch 0
    k_conv_x<<<512, 256>>>(x);                            // launch 1
    k_conv_w<<<1536, 256>>>(wih0, whh0, wihr, whhr);      // launch 2
    k_lstm<<<NCTA, NTHR, SMEM_TOTAL>>>();                 // launch 3  (ncu slot)
    k_out<<<1, 128>>>(wout, bout, y, (float*)d_out, out_size);  // launch 4
}

// round 7
// speedup vs baseline: 2.0809x; 1.2095x over previous
#include <cuda_runtime.h>
#include <cuda_fp16.h>

// ---------------------------------------------------------------------------
// HSLSTMRegressor: 3-layer LSTM (B=128, T=256, IN=64, H=512) + head + MSE.
// Layer-pipelined persistent kernel: 3 groups x 32 CTAs, group g owns layer g.
// 258 wavefront steps, one (4-way split) global barrier per step.
// R6: NTHR 256 -> 512 (16 warps, 4x4 warp grid) to fix occupancy/issue stall
// (R6 profile: issue=9.1%, occ=12.5%, nothing saturated -> latency bound).
// ---------------------------------------------------------------------------

#define Bn   128
#define Tn   256
#define INn  64
#define Hn   512
#define NCTA 96          // 3 groups x 32
#define NTHR 512
#define NSTEP (Tn + 2)   // 258 wavefront steps

// SMEM layout (bytes)
#define OFF_W 0          // 64 rows x 1032 halves (max) = 132096
#define OFF_A 132096     // 2 x 128 x 72 halves = 36864
#define OFF_G 168960     // 128 x 64 floats = 32768
#define OFF_C 201728     // 128 x 16 floats = 8192
#define OFF_B 209920     // 64 floats = 256
#define SMEM_TOTAL 210176
#define ABUF_BYTES (128 * 72 * 2)

// ---------------- device scratch (static allocations only) -----------------
__device__ __align__(16) __half g_X[Tn * Bn * INn];      // x as [t][b][k], fp16
__device__ __align__(16) __half g_W0[2048 * 576];        // layer0 [Wih|Whh], gate-interleaved
__device__ __align__(16) __half g_W12[2 * 2048 * 1024];  // layers1,2 [Wih|Whh]
__device__ __align__(16) float  g_Bias[3 * 2048];        // b_ih + b_hh, gate-interleaved
__device__ __align__(16) __half g_Hbuf[3 * 2 * Bn * Hn]; // h per layer, ping-pong on t
__device__ unsigned int g_ctr[NSTEP * 128];              // 4 counters/step, 128B apart

// ---------------------------------------------------------------------------
// launch 0: zero h/c state + barrier counters, build combined bias
__global__ void k_init_misc(const float* __restrict__ bih0, const float* __restrict__ bhh0,
                            const float* __restrict__ bihr, const float* __restrict__ bhhr) {
    int idx = blockIdx.x * blockDim.x + threadIdx.x;
    int stride = gridDim.x * blockDim.x;
    for (int i = idx; i < 3 * 2 * Bn * Hn; i += stride) g_Hbuf[i] = __float2half(0.f);
    for (int i = idx; i < NSTEP * 128; i += stride) g_ctr[i] = 0u;
    for (int i = idx; i < 3 * 2048; i += stride) {
        int l = i / 2048, r = i - l * 2048;
        int j = r >> 2, g = r & 3;
        int src = g * 512 + j;
        float v = (l == 0) ? (bih0[src] + bhh0[src])
                           : (bihr[(l - 1) * 2048 + src] + bhhr[(l - 1) * 2048 + src]);
        g_Bias[i] = v;
    }
}

// launch 1: x -> [t][b][k] fp16
__global__ void k_conv_x(const float* __restrict__ x) {
    int tot = Tn * Bn * INn;
    for (int i = blockIdx.x * blockDim.x + threadIdx.x; i < tot; i += gridDim.x * blockDim.x) {
        int t = i / (Bn * INn);
        int r = i - t * (Bn * INn);
        int b = r / INn;
        int k = r - b * INn;
        g_X[i] = __float2half(x[(size_t)b * Tn * INn + (size_t)t * INn + k]);
    }
}

// launch 2: all weights -> fp16, gate-interleaved rows (pr = 4*j + g)
__global__ void k_conv_w(const float* __restrict__ wih0, const float* __restrict__ whh0,
                         const float* __restrict__ wihr, const float* __restrict__ whhr) {
    const int W0TOT = 2048 * 576;
    const int tot = W0TOT + 2 * 2048 * 1024;
    for (int i = blockIdx.x * blockDim.x + threadIdx.x; i < tot; i += gridDim.x * blockDim.x) {
        if (i < W0TOT) {
            int r = i / 576, k = i - r * 576;
            int j = r >> 2, g = r & 3;
            int src = g * 512 + j;
            float v = (k < 64) ? wih0[src * 64 + k] : whh0[(size_t)src * 512 + (k - 64)];
            g_W0[i] = __float2half(v);
        } else {
            int rem = i - W0TOT;
            int l = rem >> 21;
            int rr = rem & ((1 << 21) - 1);
            int r = rr >> 10, k = rr & 1023;
            int j = r >> 2, g = r & 3;
            int src = g * 512 + j;
            float v = (k < 512) ? wihr[((size_t)l * 2048 + src) * 512 + k]
                                : whhr[((size_t)l * 2048 + src) * 512 + (k - 512)];
            g_W12[rem] = __float2half(v);
        }
    }
}

// ---------------------------------------------------------------------------
__device__ __forceinline__ void mma16816(float* c,
                                         unsigned a0, unsigned a1, unsigned a2, unsigned a3,
                                         unsigned b0, unsigned b1) {
    asm volatile(
        "mma.sync.aligned.m16n8k16.row.col.f32.f16.f16.f32 "
        "{%0,%1,%2,%3}, {%4,%5,%6,%7}, {%8,%9}, {%0,%1,%2,%3};\n"
        : "+f"(c[0]), "+f"(c[1]), "+f"(c[2]), "+f"(c[3])
        : "r"(a0), "r"(a1), "r"(a2), "r"(a3), "r"(b0), "r"(b1));
}

__device__ __forceinline__ void ldsm_x4(unsigned addr, unsigned& r0, unsigned& r1,
                                        unsigned& r2, unsigned& r3) {
    asm volatile("ldmatrix.sync.aligned.m8n8.x4.shared.b16 {%0,%1,%2,%3}, [%4];"
                 : "=r"(r0), "=r"(r1), "=r"(r2), "=r"(r3) : "r"(addr));
}

__device__ __forceinline__ float sigmoidf_(float x) { return 1.f / (1.f + __expf(-x)); }
__device__ __forceinline__ float tanh_fast(float x) {
    float r;
    asm("tanh.approx.f32 %0, %1;" : "=f"(r) : "f"(x));
    return r;
}

// launch 3 (== the ncu capture slot): the persistent LSTM kernel
__global__ void __launch_bounds__(NTHR, 1) k_lstm() {
    extern __shared__ __align__(16) unsigned char smraw[];
    __half* sW = (__half*)(smraw + OFF_W);
    __half* sA = (__half*)(smraw + OFF_A);
    float*  sG = (float*)(smraw + OFF_G);
    float*  sC = (float*)(smraw + OFF_C);
    float*  sB = (float*)(smraw + OFF_B);

    const int tid  = threadIdx.x;
    const int grp  = blockIdx.x >> 5;       // layer this group owns (0..2)
    const int cg   = blockIdx.x & 31;       // col group: h-cols [cg*16, cg*16+16)
    const int lane = tid & 31;
    const int wid  = tid >> 5;
    const int mrow0 = (wid & 3) * 32;       // warp's 32 batch rows (of 128)
    const int ng0   = (wid >> 2) * 16;      // warp's 16 gate rows (of 64)
    const int lg    = lane >> 2;
    const int lt2   = (lane & 3) * 2;

    const int wcols = (grp == 0) ? 576 : 1024;
    const int wstr  = (grp == 0) ? 584 : 1032;
    const __half* gW = (grp == 0) ? g_W0
                      : g_W12 + (size_t)(grp - 1) * 2048 * 1024;

    // ---- load this CTA's 64 gate rows of its layer's weights into SMEM ----
    {
        int qpr = wcols >> 3;               // uint4 per row
        for (int i = tid; i < 64 * qpr; i += NTHR) {
            int r = i / qpr, q = i - r * qpr;
            *(uint4*)(sW + r * wstr + q * 8) =
                *(const uint4*)(gW + ((size_t)(cg * 64 + r)) * wcols + q * 8);
        }
    }
    for (int i = tid; i < 64; i += NTHR) sB[i] = g_Bias[grp * 2048 + cg * 64 + i];
    for (int i = tid; i < 128 * 16; i += NTHR) sC[i] = 0.f;
    __syncthreads();

    const int arow = tid >> 2;              // A staging: 128 rows x 64 cols per chunk
    const int acs  = (tid & 3) << 4;        // 16-half (32B) segment per thread

    // ldmatrix per-lane address components
    const unsigned sA_s = (unsigned)__cvta_generic_to_shared(sA);
    const unsigned sW_s = (unsigned)__cvta_generic_to_shared(sW);
    // A x4: (r0-7,k0),(r8-15,k0),(r0-7,k8),(r8-15,k8)
    const int a_r = ((lane >> 3) & 1) * 8 + (lane & 7);
    const int a_k = (lane >> 4) * 8;
    const unsigned a_off = (unsigned)(((mrow0 + a_r) * 72 + a_k) * 2);
    // B x4: (n0-7,k0),(n0-7,k8),(n8-15,k0),(n8-15,k8)
    const int b_n = (lane & 7) + ((lane >> 4) & 1) * 8;
    const int b_k = ((lane >> 3) & 1) * 8;
    const unsigned b_off = (unsigned)(((ng0 + b_n) * wstr + b_k) * 2);

    for (int step = 0; step < NSTEP; ++step) {
        const int t = step - grp;
        if (t >= 0 && t < Tn) {
            const __half* srcA;
            int strideA, nA;
            if (grp == 0) { srcA = g_X + (size_t)t * Bn * INn; strideA = INn; nA = 1; }
            else          { srcA = g_Hbuf + ((size_t)((grp - 1) * 2 + (t & 1))) * Bn * Hn;
                            strideA = Hn; nA = 8; }
            const __half* srcB = g_Hbuf + ((size_t)(grp * 2 + ((t & 1) ^ 1))) * Bn * Hn;
            const int nch = nA + 8;

            float acc[2][2][4];
#pragma unroll
            for (int mi = 0; mi < 2; ++mi)
#pragma unroll
                for (int ni = 0; ni < 2; ++ni)
#pragma unroll
                    for (int q = 0; q < 4; ++q) acc[mi][ni][q] = 0.f;

            // depth-2 register prefetch (32B per thread per chunk)
            uint4 v[2][2];
#pragma unroll
            for (int pc = 0; pc < 2; ++pc) {
                const __half* p = (pc < nA)
                    ? srcA + (size_t)arow * strideA + (pc << 6) + acs
                    : srcB + (size_t)arow * Hn + ((pc - nA) << 6) + acs;
                v[pc][0] = __ldcg((const uint4*)p);
                v[pc][1] = __ldcg((const uint4*)(p + 8));
            }

            for (int ch = 0; ch < nch; ++ch) {
                {
                    __half* d = sA + (ch & 1) * (ABUF_BYTES / 2) + arow * 72 + acs;
                    *(uint4*)d       = v[ch & 1][0];
                    *(uint4*)(d + 8) = v[ch & 1][1];
                }
                __syncthreads();

                if (ch + 2 < nch) {
                    int c = ch + 2;
                    const __half* p = (c < nA)
                        ? srcA + (size_t)arow * strideA + (c << 6) + acs
                        : srcB + (size_t)arow * Hn + ((c - nA) << 6) + acs;
                    v[ch & 1][0] = __ldcg((const uint4*)p);
                    v[ch & 1][1] = __ldcg((const uint4*)(p + 8));
                }

                const unsigned abase = sA_s + (unsigned)((ch & 1) * ABUF_BYTES) + a_off;
                const unsigned bbase = sW_s + b_off + (unsigned)((ch << 6) * 2);
#pragma unroll
                for (int kk = 0; kk < 64; kk += 16) {
                    unsigned a0[4], a1[4], bb[4];
                    ldsm_x4(abase + kk * 2,            a0[0], a0[1], a0[2], a0[3]);
                    ldsm_x4(abase + 16 * 144 + kk * 2, a1[0], a1[1], a1[2], a1[3]);
                    ldsm_x4(bbase + kk * 2,            bb[0], bb[1], bb[2], bb[3]);
                    mma16816(acc[0][0], a0[0], a0[1], a0[2], a0[3], bb[0], bb[1]);
                    mma16816(acc[1][0], a1[0], a1[1], a1[2], a1[3], bb[0], bb[1]);
                    mma16816(acc[0][1], a0[0], a0[1], a0[2], a0[3], bb[2], bb[3]);
                    mma16816(acc[1][1], a1[0], a1[1], a1[2], a1[3], bb[2], bb[3]);
                }
            }
            __syncthreads();

            // ---- dump gate pre-activations to SMEM ----
#pragma unroll
            for (int mi = 0; mi < 2; ++mi)
#pragma unroll
                for (int ni = 0; ni < 2; ++ni) {
                    int m0 = mrow0 + mi * 16 + lg;
                    int nc = ng0 + ni * 8 + lt2;
                    sG[m0 * 64 + nc]           = acc[mi][ni][0];
                    sG[m0 * 64 + nc + 1]       = acc[mi][ni][1];
                    sG[(m0 + 8) * 64 + nc]     = acc[mi][ni][2];
                    sG[(m0 + 8) * 64 + nc + 1] = acc[mi][ni][3];
                }
            __syncthreads();

            // ---- elementwise LSTM cell: 128 batch x 16 h-cols ----
            __half* hdst = g_Hbuf + ((size_t)(grp * 2 + (t & 1))) * Bn * Hn;
            for (int idx = tid; idx < 128 * 16; idx += NTHR) {
                int m = idx >> 4, jj = idx & 15;
                float gi = sG[m * 64 + 4 * jj + 0] + sB[4 * jj + 0];
                float gf = sG[m * 64 + 4 * jj + 1] + sB[4 * jj + 1];
                float gg = sG[m * 64 + 4 * jj + 2] + sB[4 * jj + 2];
                float go = sG[m * 64 + 4 * jj + 3] + sB[4 * jj + 3];
                float cp = sC[m * 16 + jj];
                float cn = sigmoidf_(gf) * cp + sigmoidf_(gi) * tanh_fast(gg);
                float hn = sigmoidf_(go) * tanh_fast(cn);
                sC[m * 16 + jj] = cn;
                hdst[(size_t)m * Hn + cg * 16 + jj] = __float2half(hn);
            }
        }

        // ---- global wavefront barrier: 4-way split counters ----
        __threadfence();                    // release h-writes (all threads)
        __syncthreads();
        if (tid == 0)
            atomicAdd(&g_ctr[step * 128 + (blockIdx.x & 3) * 32], 1u);
        if (tid < 4) {
            volatile unsigned* pc = &g_ctr[step * 128 + tid * 32];
            long long spins = 0;
            while (*pc < (unsigned)(NCTA / 4)) {
                __nanosleep(20);
                if (++spins > (1LL << 28)) __trap();   // fail loud, never hang
            }
            __threadfence();                // acquire before reading peer h
        }
        __syncthreads();
    }
}

// ---------------------------------------------------------------------------
// launch 4: output head + MSE loss
__global__ void k_out(const float* __restrict__ wout, const float* __restrict__ bout,
                      const float* __restrict__ y, float* __restrict__ out, int out_size) {
    __shared__ float sred[128];
    int b = threadIdx.x;
    const __half* h = g_Hbuf + ((size_t)(2 * 2 + ((Tn - 1) & 1))) * Bn * Hn + (size_t)b * Hn;
    float s = 0.f;
    for (int j = 0; j < Hn; ++j) s += __half2float(h[j]) * wout[j];
    s += bout[0];
    float d = s - y[b];
    sred[b] = d * d;
    __syncthreads();
    for (int st = 64; st > 0; st >>= 1) {
        if (b < st) sred[b] += sred[b + st];
        __syncthreads();
    }
    float loss = sred[0] * (1.f / 128.f);
    if (out_size == 1) {
        if (b == 0) out[0] = loss;
    } else {
        if (b < out_size) out[b] = s;
        if (b == 0 && out_size > Bn) out[Bn] = loss;
    }
}

// ---------------------------------------------------------------------------
extern "C" void kernel_launch(void* const* d_in, const int* in_sizes, int n_in,
                              void* d_out, int out_size) {
    const float* x    = (const float*)d_in[0];
    const float* y    = (const float*)d_in[1];
    const float* wih0 = (const float*)d_in[2];
    const float* whh0 = (const float*)d_in[3];
    const float* bih0 = (const float*)d_in[4];
    const float* bhh0 = (const float*)d_in[5];
    const float* wihr = (const float*)d_in[6];
    const float* whhr = (const float*)d_in[7];
    const float* bihr = (const float*)d_in[8];
    const float* bhhr = (const float*)d_in[9];
    const float* wout = (const float*)d_in[10];
    const float* bout = (const float*)d_in[11];

    cudaFuncSetAttribute(k_lstm, cudaFuncAttributeMaxDynamicSharedMemorySize, SMEM_TOTAL);

    k_init_misc<<<512, 256>>>(bih0, bhh0, bihr, bhhr);   // launch 0
    k_conv_x<<<512, 256>>>(x);                            // launch 1
    k_conv_w<<<1536, 256>>>(wih0, whh0, wihr, whhr);      // launch 2
    k_lstm<<<NCTA, NTHR, SMEM_TOTAL>>>();                 // launch 3  (ncu slot)
    k_out<<<1, 128>>>(wout, bout, y, (float*)d_out, out_size);  // launch 4
}